// round 7
// baseline (speedup 1.0000x reference)
#include <cuda_runtime.h>
#include <cuda_bf16.h>
#include <cstdint>

#define BATCH 2048
#define CAND  16
#define DIM   256
#define ADJW  96                    // 2*3*16
#define OUTW  (DIM + ADJW + 1)      // 353
#define THRED 0.8f
#define CHUNK 32                    // batches per k_neigh block

// ---- fused sim kernel geometry ----
#define NB     8                    // batches per block
#define SLOTS  (NB + 6)             // 14 batch tiles incl. +-3 halo
#define BPAD   232                  // bf16 row stride (word stride 116 == 20 mod 32)
#define FTHR   512                  // threads (16 warps)

#define OFF_TILES  0
#define SZ_TILES   (SLOTS * CAND * BPAD * 2)            // 103936 B
#define OFF_GATES  (OFF_TILES + SZ_TILES)
#define SZ_GATES   (NB * 6 * CAND * 4)                  // 3072 B
#define OFF_RSUM   (OFF_GATES + SZ_GATES)
#define SZ_RSUM    (NB * 6 * CAND * 4)                  // 3072 B
#define OFF_INVS   (OFF_RSUM + SZ_RSUM)
#define SZ_INVS    (NB * CAND * 4)                      // 512 B
#define OFF_INVN   (OFF_INVS + SZ_INVS)
#define SZ_INVN    (SLOTS * CAND * 4)                   // 896 B
#define SMEM_TOTAL (OFF_INVN + SZ_INVN)                 // 111488 B -> 2 CTAs/SM

// ---------------------------------------------------------------------------
// K_neigh: neighbor-mean (output cols [0,256)). Rolling 7-batch window.
// ---------------------------------------------------------------------------
__global__ __launch_bounds__(256) void k_neigh(const float* __restrict__ emb,
                                               const int* __restrict__ nm,
                                               float* __restrict__ out) {
    const int d4 = threadIdx.x;                       // 0..63
    const int c  = blockIdx.y * 4 + threadIdx.y;      // 0..15
    const int b0 = blockIdx.x * CHUNK;

    auto loadE = [&](int bb) -> float4 {
        if ((unsigned)bb < BATCH)
            return reinterpret_cast<const float4*>(emb)[((size_t)bb * CAND + c) * (DIM / 4) + d4];
        return make_float4(0.f, 0.f, 0.f, 0.f);
    };
    auto loadM = [&](int bb) -> float {
        if ((unsigned)bb < BATCH) return (float)nm[bb * CAND + c];
        return 0.f;
    };

    float4 w[7];
    float  m[6];
    #pragma unroll
    for (int i = 0; i < 7; i++) w[i] = loadE(b0 - 3 + i);
    #pragma unroll
    for (int i = 0; i < 6; i++) m[i] = loadM(b0 - 3 + i);

    #pragma unroll 8
    for (int s = 0; s < CHUNK; s++) {
        const int b = b0 + s;
        const float L1 = m[2], L2 = m[2] * m[1], L3 = m[2] * m[1] * m[0];
        const float R1 = m[3], R2 = m[3] * m[4], R3 = m[3] * m[4] * m[5];
        float4 acc;
        acc.x = (w[2].x*L1 + w[1].x*L2 + w[0].x*L3 + w[4].x*R1 + w[5].x*R2 + w[6].x*R3) * (1.f/6.f);
        acc.y = (w[2].y*L1 + w[1].y*L2 + w[0].y*L3 + w[4].y*R1 + w[5].y*R2 + w[6].y*R3) * (1.f/6.f);
        acc.z = (w[2].z*L1 + w[1].z*L2 + w[0].z*L3 + w[4].z*R1 + w[5].z*R2 + w[6].z*R3) * (1.f/6.f);
        acc.w = (w[2].w*L1 + w[1].w*L2 + w[0].w*L3 + w[4].w*R1 + w[5].w*R2 + w[6].w*R3) * (1.f/6.f);
        float* o = out + (size_t)(b * CAND + c) * OUTW + d4 * 4;
        o[0] = acc.x; o[1] = acc.y; o[2] = acc.z; o[3] = acc.w;
        #pragma unroll
        for (int i = 0; i < 6; i++) w[i] = w[i + 1];
        w[6] = loadE(b + 4);
        #pragma unroll
        for (int i = 0; i < 5; i++) m[i] = m[i + 1];
        m[5] = loadM(b + 3);
    }
}

// ---------------------------------------------------------------------------
// K_fused: band cosine adjacency (output cols [256,353)).
// Deferred normalization: tiles hold RAW bf16 rows (pure streaming copy),
// per-row inverse norms come from self-product MMA diagonals (free operand
// reuse: B frags == A frags). Epilogue scales dot by invn_a*invn_b, then
// threshold/gate/L1-normalize.
// ---------------------------------------------------------------------------
__global__ __launch_bounds__(FTHR, 2) void k_fused(const float* __restrict__ emb,
                                                   const int* __restrict__ nm,
                                                   float* __restrict__ out) {
    extern __shared__ __align__(16) char smraw[];
    __nv_bfloat16* tiles = reinterpret_cast<__nv_bfloat16*>(smraw + OFF_TILES); // [14][16][BPAD]
    float* gates = reinterpret_cast<float*>(smraw + OFF_GATES);                 // [NB][6][16]
    float* rsum  = reinterpret_cast<float*>(smraw + OFF_RSUM);                  // [NB][6][16]
    float* invs  = reinterpret_cast<float*>(smraw + OFF_INVS);                  // [NB][16]
    float* invn  = reinterpret_cast<float*>(smraw + OFF_INVN);                  // [14][16]

    const int b0   = blockIdx.x * NB;
    const int t    = threadIdx.x;
    const int wid  = t >> 5;
    const int lane = t & 31;

    // ---- streaming copy+cast: 224 rows, no per-row reduction ----
    const int l8 = lane * 8;
    #pragma unroll 4
    for (int r = wid; r < SLOTS * CAND; r += 16) {
        const int bb = b0 - 3 + (r >> 4);
        float4 v0 = make_float4(0.f, 0.f, 0.f, 0.f);
        float4 v1 = v0;
        if ((unsigned)bb < BATCH) {
            const float4* src = reinterpret_cast<const float4*>(
                emb + ((size_t)bb * CAND + (r & 15)) * DIM);
            v0 = src[lane * 2];
            v1 = src[lane * 2 + 1];
        }
        __nv_bfloat162 o[4];
        o[0] = __floats2bfloat162_rn(v0.x, v0.y);
        o[1] = __floats2bfloat162_rn(v0.z, v0.w);
        o[2] = __floats2bfloat162_rn(v1.x, v1.y);
        o[3] = __floats2bfloat162_rn(v1.z, v1.w);
        *reinterpret_cast<uint4*>(&tiles[(size_t)r * BPAD + l8]) = *reinterpret_cast<uint4*>(o);
    }

    // ---- gates: [bi][cp][j]; cp 0..2 = left k=1..3, 3..5 = right k=1..3 ----
    for (int idx = t; idx < NB * 6 * CAND; idx += FTHR) {
        const int bi = idx / (6 * CAND);
        const int rem = idx % (6 * CAND);
        const int cp = rem >> 4, j = rem & 15;
        const int b = b0 + bi;
        float g = 1.f;
        if (cp < 3) {
            const int k = cp + 1;
            if (b - k < 0) g = 0.f;
            else { for (int q = 1; q <= k; q++) g *= (float)nm[(b - q) * CAND + j]; }
        } else {
            const int k = cp - 2;
            if (b + k >= BATCH) g = 0.f;
            else { for (int q = 0; q < k; q++) g *= (float)nm[(b + q) * CAND + j]; }
        }
        gates[idx] = g;
    }
    __syncthreads();

    const int g  = lane >> 2;           // 0..7
    const int tg = lane & 3;            // 0..3
    const int jb = tg * 2;

    // ---- self-product MMAs: warps 0..13 compute invn for tile wid ----
    if (wid < SLOTS) {
        const __nv_bfloat16* S = &tiles[(size_t)wid * CAND * BPAD];
        float s0[4] = {0.f, 0.f, 0.f, 0.f};
        float s1[4] = {0.f, 0.f, 0.f, 0.f};
        #pragma unroll
        for (int kt = 0; kt < 16; kt++) {
            const int k0 = kt * 16 + jb;
            const uint32_t sa0 = *(const uint32_t*)&S[g * BPAD + k0];
            const uint32_t sa1 = *(const uint32_t*)&S[(g + 8) * BPAD + k0];
            const uint32_t sa2 = *(const uint32_t*)&S[g * BPAD + k0 + 8];
            const uint32_t sa3 = *(const uint32_t*)&S[(g + 8) * BPAD + k0 + 8];
            asm volatile(
                "mma.sync.aligned.m16n8k16.row.col.f32.bf16.bf16.f32 "
                "{%0,%1,%2,%3}, {%4,%5,%6,%7}, {%8,%9}, {%0,%1,%2,%3};\n"
                : "+f"(s0[0]), "+f"(s0[1]), "+f"(s0[2]), "+f"(s0[3])
                : "r"(sa0), "r"(sa1), "r"(sa2), "r"(sa3), "r"(sa0), "r"(sa2));
            asm volatile(
                "mma.sync.aligned.m16n8k16.row.col.f32.bf16.bf16.f32 "
                "{%0,%1,%2,%3}, {%4,%5,%6,%7}, {%8,%9}, {%0,%1,%2,%3};\n"
                : "+f"(s1[0]), "+f"(s1[1]), "+f"(s1[2]), "+f"(s1[3])
                : "r"(sa0), "r"(sa1), "r"(sa2), "r"(sa3), "r"(sa1), "r"(sa3));
        }
        // diag extraction: lane with tg == g>>1 holds D[g][g] and D[g+8][g+8]
        if (tg == (g >> 1)) {
            invn[wid * CAND + g]     = rsqrtf(fmaxf((g & 1) ? s0[1] : s0[0], 1e-12f));
            invn[wid * CAND + g + 8] = rsqrtf(fmaxf((g & 1) ? s1[3] : s1[2], 1e-12f));
        }
    }

    // ---- pair MMAs: warp wid -> bi = wid/2, cps {0,1,2} or {3,4,5} ----
    const int bi = wid >> 1;            // 0..7
    const int cpb = (wid & 1) * 3;      // 0 or 3
    const int aslot = bi + 3;

    const __nv_bfloat16* A = &tiles[(size_t)aslot * CAND * BPAD];
    int bslot[3];
    const __nv_bfloat16* Bp[3];
    #pragma unroll
    for (int e = 0; e < 3; e++) {
        const int cp = cpb + e;
        bslot[e] = (cp < 3) ? (bi + 2 - cp) : (bi + 1 + cp);
        Bp[e] = &tiles[(size_t)bslot[e] * CAND * BPAD];
    }

    float acc[3][8];
    #pragma unroll
    for (int e = 0; e < 3; e++)
        #pragma unroll
        for (int x = 0; x < 8; x++) acc[e][x] = 0.f;

    #pragma unroll
    for (int kt = 0; kt < 16; kt++) {
        const int k0 = kt * 16 + jb;
        const uint32_t ra0 = *(const uint32_t*)&A[g * BPAD + k0];
        const uint32_t ra1 = *(const uint32_t*)&A[(g + 8) * BPAD + k0];
        const uint32_t ra2 = *(const uint32_t*)&A[g * BPAD + k0 + 8];
        const uint32_t ra3 = *(const uint32_t*)&A[(g + 8) * BPAD + k0 + 8];
        #pragma unroll
        for (int e = 0; e < 3; e++) {
            const uint32_t rb0 = *(const uint32_t*)&Bp[e][g * BPAD + k0];
            const uint32_t rb1 = *(const uint32_t*)&Bp[e][g * BPAD + k0 + 8];
            const uint32_t rc0 = *(const uint32_t*)&Bp[e][(g + 8) * BPAD + k0];
            const uint32_t rc1 = *(const uint32_t*)&Bp[e][(g + 8) * BPAD + k0 + 8];
            asm volatile(
                "mma.sync.aligned.m16n8k16.row.col.f32.bf16.bf16.f32 "
                "{%0,%1,%2,%3}, {%4,%5,%6,%7}, {%8,%9}, {%0,%1,%2,%3};\n"
                : "+f"(acc[e][0]), "+f"(acc[e][1]), "+f"(acc[e][2]), "+f"(acc[e][3])
                : "r"(ra0), "r"(ra1), "r"(ra2), "r"(ra3), "r"(rb0), "r"(rb1));
            asm volatile(
                "mma.sync.aligned.m16n8k16.row.col.f32.bf16.bf16.f32 "
                "{%0,%1,%2,%3}, {%4,%5,%6,%7}, {%8,%9}, {%0,%1,%2,%3};\n"
                : "+f"(acc[e][4]), "+f"(acc[e][5]), "+f"(acc[e][6]), "+f"(acc[e][7])
                : "r"(ra0), "r"(ra1), "r"(ra2), "r"(ra3), "r"(rc0), "r"(rc1));
        }
    }
    __syncthreads();   // invn complete block-wide

    // ---- epilogue: scale by invn, threshold, gate, partial row sums ----
    const float inA0 = invn[aslot * CAND + g];
    const float inA8 = invn[aslot * CAND + g + 8];
    #pragma unroll
    for (int e = 0; e < 3; e++) {
        const int cp = cpb + e;
        const float* np = &invn[bslot[e] * CAND];
        const float ib0 = np[jb], ib1 = np[jb + 1], ib8 = np[jb + 8], ib9 = np[jb + 9];
        const float* gp = &gates[(bi * 6 + cp) * CAND];
        const float g0 = gp[jb], g1 = gp[jb + 1], g2 = gp[jb + 8], g3 = gp[jb + 9];
        auto thr = [](float v, float ge) {
            v = (v > THRED) ? fminf(v, 1.f) : 0.f;
            return v * ge;
        };
        acc[e][0] = thr(acc[e][0] * inA0 * ib0, g0);
        acc[e][1] = thr(acc[e][1] * inA0 * ib1, g1);
        acc[e][2] = thr(acc[e][2] * inA8 * ib0, g0);
        acc[e][3] = thr(acc[e][3] * inA8 * ib1, g1);
        acc[e][4] = thr(acc[e][4] * inA0 * ib8, g2);
        acc[e][5] = thr(acc[e][5] * inA0 * ib9, g3);
        acc[e][6] = thr(acc[e][6] * inA8 * ib8, g2);
        acc[e][7] = thr(acc[e][7] * inA8 * ib9, g3);

        float sA = acc[e][0] + acc[e][1] + acc[e][4] + acc[e][5]; // row g
        float sB = acc[e][2] + acc[e][3] + acc[e][6] + acc[e][7]; // row g+8
        sA += __shfl_xor_sync(0xffffffffu, sA, 1);
        sA += __shfl_xor_sync(0xffffffffu, sA, 2);
        sB += __shfl_xor_sync(0xffffffffu, sB, 1);
        sB += __shfl_xor_sync(0xffffffffu, sB, 2);
        if (tg == 0) {
            rsum[(bi * 6 + cp) * CAND + g]     = sA;
            rsum[(bi * 6 + cp) * CAND + g + 8] = sB;
        }
    }
    __syncthreads();

    // ---- invs: per output row 1 / (L1 sum + ones col) ----
    if (t < NB * CAND) {
        const int tb = t >> 4, i = t & 15;
        float s = 1.0f;
        #pragma unroll
        for (int cp = 0; cp < 6; cp++) s += rsum[(tb * 6 + cp) * CAND + i];
        invs[t] = 1.0f / fmaxf(s, 1e-12f);
    }
    __syncthreads();

    // ---- normalized writes ----
    const float ivA = invs[bi * 16 + g];
    const float ivB = invs[bi * 16 + g + 8];
    #pragma unroll
    for (int e = 0; e < 3; e++) {
        const int cp = cpb + e;
        float* oA = out + (size_t)((b0 + bi) * CAND + g)     * OUTW + DIM + cp * CAND + jb;
        float* oB = out + (size_t)((b0 + bi) * CAND + g + 8) * OUTW + DIM + cp * CAND + jb;
        oA[0] = acc[e][0] * ivA;  oA[1] = acc[e][1] * ivA;
        oA[8] = acc[e][4] * ivA;  oA[9] = acc[e][5] * ivA;
        oB[0] = acc[e][2] * ivB;  oB[1] = acc[e][3] * ivB;
        oB[8] = acc[e][6] * ivB;  oB[9] = acc[e][7] * ivB;
    }
    if (t < NB * CAND) {
        out[(size_t)(b0 * CAND + t) * OUTW + DIM + ADJW] = invs[t];  // ones column * inv
    }
}

// ---------------------------------------------------------------------------
extern "C" void kernel_launch(void* const* d_in, const int* in_sizes, int n_in,
                              void* d_out, int out_size) {
    (void)in_sizes; (void)n_in; (void)out_size;
    const float* emb = (const float*)d_in[0];
    const int*   nm  = (const int*)d_in[1];
    float*       out = (float*)d_out;

    (void)cudaFuncSetAttribute(k_fused, cudaFuncAttributeMaxDynamicSharedMemorySize,
                               SMEM_TOTAL);

    dim3 nb(64, 4);
    dim3 ng(BATCH / CHUNK, 4);
    k_neigh<<<ng, nb>>>(emb, nm, out);

    k_fused<<<BATCH / NB, FTHR, SMEM_TOTAL>>>(emb, nm, out);
}

// round 8
// speedup vs baseline: 1.0555x; 1.0555x over previous
#include <cuda_runtime.h>
#include <cuda_bf16.h>
#include <cstdint>

#define BATCH 2048
#define CAND  16
#define DIM   256
#define ADJW  96                    // 2*3*16
#define OUTW  (DIM + ADJW + 1)      // 353
#define THRED 0.8f
#define CHUNK 32                    // batches per k_neigh block

// ---- fused sim kernel geometry ----
#define NB     7                    // batches per block
#define SLOTS  (NB + 6)             // 13 batch tiles incl. +-3 halo
#define BPAD   264                  // bf16 row stride (>=256; 264%32==8 -> ldsm bank-clean)
#define FTHR   448                  // threads (14 warps)

#define OFF_TILES  0
#define SZ_TILES   (SLOTS * CAND * BPAD * 2)            // 109824 B
#define OFF_RSUM   (OFF_TILES + SZ_TILES)
#define SZ_RSUM    (NB * 6 * CAND * 4)                  // 2688 B
#define OFF_INVS   (OFF_RSUM + SZ_RSUM)
#define SZ_INVS    (NB * CAND * 4)                      // 448 B
#define OFF_INVN   (OFF_INVS + SZ_INVS)
#define SZ_INVN    (SLOTS * CAND * 4)                   // 832 B
#define OFF_NMV    (OFF_INVN + SZ_INVN)
#define SZ_NMV     (SLOTS * CAND * 4)                   // 832 B
#define SMEM_TOTAL (OFF_NMV + SZ_NMV)                   // 114624 B -> 2 CTAs/SM

#define FGRID ((BATCH + NB - 1) / NB)                   // 293 blocks ~ one wave

__device__ __forceinline__ uint32_t smem_u32(const void* p) {
    uint32_t a;
    asm("{ .reg .u64 t; cvta.to.shared.u64 t, %1; cvt.u32.u64 %0, t; }"
        : "=r"(a) : "l"(p));
    return a;
}

__device__ __forceinline__ void ldsm4(uint32_t addr, uint32_t& r0, uint32_t& r1,
                                      uint32_t& r2, uint32_t& r3) {
    asm volatile("ldmatrix.sync.aligned.m8n8.x4.shared.b16 {%0,%1,%2,%3}, [%4];"
                 : "=r"(r0), "=r"(r1), "=r"(r2), "=r"(r3) : "r"(addr));
}

__device__ __forceinline__ void mma16816(float* c, uint32_t a0, uint32_t a1,
                                         uint32_t a2, uint32_t a3,
                                         uint32_t b0, uint32_t b1) {
    asm volatile(
        "mma.sync.aligned.m16n8k16.row.col.f32.bf16.bf16.f32 "
        "{%0,%1,%2,%3}, {%4,%5,%6,%7}, {%8,%9}, {%0,%1,%2,%3};\n"
        : "+f"(c[0]), "+f"(c[1]), "+f"(c[2]), "+f"(c[3])
        : "r"(a0), "r"(a1), "r"(a2), "r"(a3), "r"(b0), "r"(b1));
}

// ---------------------------------------------------------------------------
// K_neigh: neighbor-mean (output cols [0,256)). Rolling 7-batch window.
// ---------------------------------------------------------------------------
__global__ __launch_bounds__(256) void k_neigh(const float* __restrict__ emb,
                                               const int* __restrict__ nm,
                                               float* __restrict__ out) {
    const int d4 = threadIdx.x;                       // 0..63
    const int c  = blockIdx.y * 4 + threadIdx.y;      // 0..15
    const int b0 = blockIdx.x * CHUNK;

    auto loadE = [&](int bb) -> float4 {
        if ((unsigned)bb < BATCH)
            return reinterpret_cast<const float4*>(emb)[((size_t)bb * CAND + c) * (DIM / 4) + d4];
        return make_float4(0.f, 0.f, 0.f, 0.f);
    };
    auto loadM = [&](int bb) -> float {
        if ((unsigned)bb < BATCH) return (float)nm[bb * CAND + c];
        return 0.f;
    };

    float4 w[7];
    float  m[6];
    #pragma unroll
    for (int i = 0; i < 7; i++) w[i] = loadE(b0 - 3 + i);
    #pragma unroll
    for (int i = 0; i < 6; i++) m[i] = loadM(b0 - 3 + i);

    #pragma unroll 8
    for (int s = 0; s < CHUNK; s++) {
        const int b = b0 + s;
        const float L1 = m[2], L2 = m[2] * m[1], L3 = m[2] * m[1] * m[0];
        const float R1 = m[3], R2 = m[3] * m[4], R3 = m[3] * m[4] * m[5];
        float4 acc;
        acc.x = (w[2].x*L1 + w[1].x*L2 + w[0].x*L3 + w[4].x*R1 + w[5].x*R2 + w[6].x*R3) * (1.f/6.f);
        acc.y = (w[2].y*L1 + w[1].y*L2 + w[0].y*L3 + w[4].y*R1 + w[5].y*R2 + w[6].y*R3) * (1.f/6.f);
        acc.z = (w[2].z*L1 + w[1].z*L2 + w[0].z*L3 + w[4].z*R1 + w[5].z*R2 + w[6].z*R3) * (1.f/6.f);
        acc.w = (w[2].w*L1 + w[1].w*L2 + w[0].w*L3 + w[4].w*R1 + w[5].w*R2 + w[6].w*R3) * (1.f/6.f);
        float* o = out + (size_t)(b * CAND + c) * OUTW + d4 * 4;
        o[0] = acc.x; o[1] = acc.y; o[2] = acc.z; o[3] = acc.w;
        #pragma unroll
        for (int i = 0; i < 6; i++) w[i] = w[i + 1];
        w[6] = loadE(b + 4);
        #pragma unroll
        for (int i = 0; i < 5; i++) m[i] = m[i + 1];
        m[5] = loadM(b + 3);
    }
}

// ---------------------------------------------------------------------------
// K_fused: band cosine adjacency (output cols [256,353)).
// Raw bf16 tiles (streaming copy); norms via self-product MMA diagonals;
// ldmatrix fragment loads; gates computed from an smem mask cache.
// OOB batches are zero tiles + zero masks => boundary sims are exactly 0.
// ---------------------------------------------------------------------------
__global__ __launch_bounds__(FTHR, 2) void k_fused(const float* __restrict__ emb,
                                                   const int* __restrict__ nm,
                                                   float* __restrict__ out) {
    extern __shared__ __align__(16) char smraw[];
    __nv_bfloat16* tiles = reinterpret_cast<__nv_bfloat16*>(smraw + OFF_TILES); // [13][16][BPAD]
    float* rsum = reinterpret_cast<float*>(smraw + OFF_RSUM);                   // [NB][6][16]
    float* invs = reinterpret_cast<float*>(smraw + OFF_INVS);                   // [NB][16]
    float* invn = reinterpret_cast<float*>(smraw + OFF_INVN);                   // [13][16]
    float* nmv  = reinterpret_cast<float*>(smraw + OFF_NMV);                    // [13][16]

    const int b0   = blockIdx.x * NB;
    const int t    = threadIdx.x;
    const int wid  = t >> 5;
    const int lane = t & 31;

    // ---- streaming copy+cast: 208 rows ----
    const int l8 = lane * 8;
    for (int r = wid; r < SLOTS * CAND; r += FTHR / 32) {
        const int bb = b0 - 3 + (r >> 4);
        float4 v0 = make_float4(0.f, 0.f, 0.f, 0.f);
        float4 v1 = v0;
        if ((unsigned)bb < BATCH) {
            const float4* src = reinterpret_cast<const float4*>(
                emb + ((size_t)bb * CAND + (r & 15)) * DIM);
            v0 = src[lane * 2];
            v1 = src[lane * 2 + 1];
        }
        __nv_bfloat162 o[4];
        o[0] = __floats2bfloat162_rn(v0.x, v0.y);
        o[1] = __floats2bfloat162_rn(v0.z, v0.w);
        o[2] = __floats2bfloat162_rn(v1.x, v1.y);
        o[3] = __floats2bfloat162_rn(v1.z, v1.w);
        *reinterpret_cast<uint4*>(&tiles[(size_t)r * BPAD + l8]) = *reinterpret_cast<uint4*>(o);
    }

    // ---- mask cache: nmv[slot][j] (OOB batches -> 0) ----
    if (t < SLOTS * CAND) {
        const int bb = b0 - 3 + (t >> 4);
        nmv[t] = ((unsigned)bb < BATCH) ? (float)nm[bb * CAND + (t & 15)] : 0.f;
    }
    __syncthreads();

    const int g  = lane >> 2;           // 0..7
    const int tg = lane & 3;            // 0..3
    const int jb = tg * 2;
    // ldmatrix per-lane row address offset within a tile (elements)
    const int lmoff = (lane & 15) * BPAD + (lane >> 4) * 8;
    const uint32_t tiles_base = smem_u32(tiles);

    // ---- self-product MMAs: warps 0..12 compute invn for tile wid ----
    if (wid < SLOTS) {
        uint32_t sad = tiles_base + (uint32_t)(wid * CAND * BPAD + lmoff) * 2;
        float s0[4] = {0.f, 0.f, 0.f, 0.f};
        float s1[4] = {0.f, 0.f, 0.f, 0.f};
        #pragma unroll
        for (int kt = 0; kt < 16; kt++) {
            uint32_t a0, a1, a2, a3;
            ldsm4(sad, a0, a1, a2, a3);
            sad += 32;
            mma16816(s0, a0, a1, a2, a3, a0, a2);
            mma16816(s1, a0, a1, a2, a3, a1, a3);
        }
        if (tg == (g >> 1)) {
            invn[wid * CAND + g]     = rsqrtf(fmaxf((g & 1) ? s0[1] : s0[0], 1e-12f));
            invn[wid * CAND + g + 8] = rsqrtf(fmaxf((g & 1) ? s1[3] : s1[2], 1e-12f));
        }
    }

    // ---- pair MMAs: warp wid -> bi = wid/2, cps {0,1,2} or {3,4,5} ----
    const int bi = wid >> 1;            // 0..6
    const int cpb = (wid & 1) * 3;      // 0 (left) or 3 (right)
    const int slot = bi + 3;            // center tile slot

    uint32_t aad = tiles_base + (uint32_t)(slot * CAND * BPAD + lmoff) * 2;
    int bslot[3];
    uint32_t bad[3];
    #pragma unroll
    for (int e = 0; e < 3; e++) {
        bslot[e] = (cpb == 0) ? (slot - 1 - e) : (slot + 1 + e);
        bad[e] = tiles_base + (uint32_t)(bslot[e] * CAND * BPAD + lmoff) * 2;
    }

    float acc[3][8];
    #pragma unroll
    for (int e = 0; e < 3; e++)
        #pragma unroll
        for (int x = 0; x < 8; x++) acc[e][x] = 0.f;

    #pragma unroll
    for (int kt = 0; kt < 16; kt++) {
        uint32_t a0, a1, a2, a3;
        ldsm4(aad, a0, a1, a2, a3);
        aad += 32;
        #pragma unroll
        for (int e = 0; e < 3; e++) {
            uint32_t m0, m1, m2, m3;    // {B[g][k0], B[g+8][k0], B[g][k0+8], B[g+8][k0+8]}
            ldsm4(bad[e], m0, m1, m2, m3);
            bad[e] += 32;
            mma16816(acc[e],     a0, a1, a2, a3, m0, m2);   // cols jb..: n = g
            mma16816(acc[e] + 4, a0, a1, a2, a3, m1, m3);   // cols jb+8..: n = g+8
        }
    }
    __syncthreads();   // invn + nmv complete block-wide

    // ---- gates from mask cache: per j, cumulative products toward the side ----
    float gj[4][3];
    const int js[4] = {jb, jb + 1, jb + 8, jb + 9};
    #pragma unroll
    for (int jx = 0; jx < 4; jx++) {
        float a, b, c;
        if (cpb == 0) {         // left: masks of batches b-1, b-2, b-3
            a = nmv[(slot - 1) * CAND + js[jx]];
            b = nmv[(slot - 2) * CAND + js[jx]];
            c = nmv[(slot - 3) * CAND + js[jx]];
        } else {                // right: masks of batches b, b+1, b+2
            a = nmv[slot * CAND + js[jx]];
            b = nmv[(slot + 1) * CAND + js[jx]];
            c = nmv[(slot + 2) * CAND + js[jx]];
        }
        gj[jx][0] = a;
        gj[jx][1] = a * b;
        gj[jx][2] = a * b * c;
    }

    // ---- epilogue: cosine scale, threshold, gate, partial row sums ----
    const float inA0 = invn[slot * CAND + g];
    const float inA8 = invn[slot * CAND + g + 8];
    #pragma unroll
    for (int e = 0; e < 3; e++) {
        const int cp = cpb + e;
        const float* np = &invn[bslot[e] * CAND];
        const float ib0 = np[jb], ib1 = np[jb + 1], ib8 = np[jb + 8], ib9 = np[jb + 9];
        auto thr = [](float v, float ge) {
            v = (v > THRED) ? fminf(v, 1.f) : 0.f;
            return v * ge;
        };
        acc[e][0] = thr(acc[e][0] * inA0 * ib0, gj[0][e]);
        acc[e][1] = thr(acc[e][1] * inA0 * ib1, gj[1][e]);
        acc[e][2] = thr(acc[e][2] * inA8 * ib0, gj[0][e]);
        acc[e][3] = thr(acc[e][3] * inA8 * ib1, gj[1][e]);
        acc[e][4] = thr(acc[e][4] * inA0 * ib8, gj[2][e]);
        acc[e][5] = thr(acc[e][5] * inA0 * ib9, gj[3][e]);
        acc[e][6] = thr(acc[e][6] * inA8 * ib8, gj[2][e]);
        acc[e][7] = thr(acc[e][7] * inA8 * ib9, gj[3][e]);

        float sA = acc[e][0] + acc[e][1] + acc[e][4] + acc[e][5]; // row g
        float sB = acc[e][2] + acc[e][3] + acc[e][6] + acc[e][7]; // row g+8
        sA += __shfl_xor_sync(0xffffffffu, sA, 1);
        sA += __shfl_xor_sync(0xffffffffu, sA, 2);
        sB += __shfl_xor_sync(0xffffffffu, sB, 1);
        sB += __shfl_xor_sync(0xffffffffu, sB, 2);
        if (tg == 0) {
            rsum[(bi * 6 + cp) * CAND + g]     = sA;
            rsum[(bi * 6 + cp) * CAND + g + 8] = sB;
        }
    }
    __syncthreads();

    // ---- invs: per output row 1 / (L1 sum + ones col) ----
    if (t < NB * CAND) {
        const int tb = t >> 4, i = t & 15;
        float s = 1.0f;
        #pragma unroll
        for (int cp = 0; cp < 6; cp++) s += rsum[(tb * 6 + cp) * CAND + i];
        invs[t] = 1.0f / fmaxf(s, 1e-12f);
    }
    __syncthreads();

    // ---- normalized writes (guard partial last block) ----
    if (b0 + bi < BATCH) {
        const float ivA = invs[bi * CAND + g];
        const float ivB = invs[bi * CAND + g + 8];
        #pragma unroll
        for (int e = 0; e < 3; e++) {
            const int cp = cpb + e;
            float* oA = out + (size_t)((b0 + bi) * CAND + g)     * OUTW + DIM + cp * CAND + jb;
            float* oB = out + (size_t)((b0 + bi) * CAND + g + 8) * OUTW + DIM + cp * CAND + jb;
            oA[0] = acc[e][0] * ivA;  oA[1] = acc[e][1] * ivA;
            oA[8] = acc[e][4] * ivA;  oA[9] = acc[e][5] * ivA;
            oB[0] = acc[e][2] * ivB;  oB[1] = acc[e][3] * ivB;
            oB[8] = acc[e][6] * ivB;  oB[9] = acc[e][7] * ivB;
        }
    }
    if (t < NB * CAND && b0 + (t >> 4) < BATCH) {
        out[(size_t)(b0 * CAND + t) * OUTW + DIM + ADJW] = invs[t];  // ones column * inv
    }
}

// ---------------------------------------------------------------------------
extern "C" void kernel_launch(void* const* d_in, const int* in_sizes, int n_in,
                              void* d_out, int out_size) {
    (void)in_sizes; (void)n_in; (void)out_size;
    const float* emb = (const float*)d_in[0];
    const int*   nm  = (const int*)d_in[1];
    float*       out = (float*)d_out;

    (void)cudaFuncSetAttribute(k_fused, cudaFuncAttributeMaxDynamicSharedMemorySize,
                               SMEM_TOTAL);

    dim3 nb(64, 4);
    dim3 ng(BATCH / CHUNK, 4);
    k_neigh<<<ng, nb>>>(emb, nm, out);

    k_fused<<<FGRID, FTHR, SMEM_TOTAL>>>(emb, nm, out);
}